// round 5
// baseline (speedup 1.0000x reference)
#include <cuda_runtime.h>
#include <math.h>

#define N_IMG   512
#define N_ANG   25
#define N_DET   512
#define N_SAMP  1024
#define N_RAYS  (N_ANG * N_DET)

#define SRC_DIST 512.0f
#define DET_DIST 512.0f
#define DET_SPACING 3.0f

// quad tables: one LDG.128 yields all 4 bilinear texels.
// g_quad [g*512+f] = (img[g][f],  img[g][f+1],  img[g+1][f],  img[g+1][f+1])   g=row, f=col
// g_quadT[g*512+f] = (img[f][g],  img[f+1][g],  img[f][g+1],  img[f+1][g+1])   g=col, f=row
//   layout contract: .x=(g,f)  .y=(g,f+1)  .z=(g+1,f)  .w=(g+1,f+1) in (slow g, fast f) coords
__device__ float4 g_quad [N_IMG * N_IMG];
__device__ float4 g_quadT[N_IMG * N_IMG];

__global__ __launch_bounds__(256)
void prep_kernel(const float* __restrict__ img) {
    __shared__ float tile[33][35];   // rows 0..32, cols 0..32 (+pad: stride 35 -> conflict-free transpose)
    int bx = blockIdx.x * 32;        // col base
    int by = blockIdx.y * 32;        // row base
    int tx = threadIdx.x;            // 0..31
    int ty = threadIdx.y;            // 0..7

    for (int r = ty; r < 33; r += 8) {
        int gr = by + r;
        bool rok = gr < N_IMG;
        tile[r][tx] = rok ? img[gr * N_IMG + bx + tx] : 0.0f;
        if (tx == 0) {
            int gc = bx + 32;
            tile[r][32] = (rok && gc < N_IMG) ? img[gr * N_IMG + gc] : 0.0f;
        }
    }
    __syncthreads();

    // row-major quads (g=row, f=col): coalesced over tx
    #pragma unroll
    for (int r = ty; r < 32; r += 8)
        g_quad[(by + r) * N_IMG + bx + tx] =
            make_float4(tile[r][tx], tile[r][tx + 1], tile[r + 1][tx], tile[r + 1][tx + 1]);

    // col-major quads (g=col, f=row): write index (bx+cc)*512 + (by+tx), coalesced over tx
    // .x=(g,f)=img[f][g]=tile[tx][cc]  .y=(g,f+1)=tile[tx+1][cc]
    // .z=(g+1,f)=tile[tx][cc+1]        .w=(g+1,f+1)=tile[tx+1][cc+1]
    #pragma unroll
    for (int cc = ty; cc < 32; cc += 8)
        g_quadT[(bx + cc) * N_IMG + by + tx] =
            make_float4(tile[tx][cc], tile[tx + 1][cc], tile[tx][cc + 1], tile[tx + 1][cc + 1]);
}

// shrink [u0,u1] so that p + u*v stays within [lo, hi]
__device__ __forceinline__ void clip_axis(float p, float v, float lo, float hi,
                                          float& u0, float& u1) {
    if (fabsf(v) < 1e-12f) {
        if (p < lo || p > hi) { u0 = 1e30f; u1 = -1e30f; }
    } else {
        float inv = 1.0f / v;
        float a = (lo - p) * inv;
        float b = (hi - p) * inv;
        float mn = fminf(a, b), mx = fmaxf(a, b);
        u0 = fmaxf(u0, mn);
        u1 = fminf(u1, mx);
    }
}

__device__ __forceinline__ float fetch_masked(const float* __restrict__ img, int r, int c) {
    bool ok = (r >= 0) & (r < N_IMG) & (c >= 0) & (c < N_IMG);
    int rr = min(max(r, 0), N_IMG - 1);
    int cc = min(max(c, 0), N_IMG - 1);
    float v = __ldg(img + rr * N_IMG + cc);
    return ok ? v : 0.0f;
}

__global__ __launch_bounds__(256)
void fanbeam_kernel(const float* __restrict__ img, float* __restrict__ out) {
    int gwarp = blockIdx.x * 8 + (threadIdx.x >> 5);
    int lane  = threadIdx.x & 31;

    int a = gwarp / N_DET;
    int d = gwarp - a * N_DET;

    float beta = (float)a * (2.0f * 3.14159265358979323846f / (float)N_ANG);
    float s, c;
    sincosf(beta, &s, &c);

    float t  = ((float)d - (float)(N_DET - 1) * 0.5f) * DET_SPACING;
    float sx = -SRC_DIST * s;
    float sy =  SRC_DIST * c;
    float ex = t * c + DET_DIST * s;
    float ey = t * s - DET_DIST * c;
    float dx = ex - sx;
    float dy = ey - sy;
    float seg = sqrtf(dx * dx + dy * dy);

    const float half  = (float)(N_IMG - 1) * 0.5f;   // 255.5
    const float inv_s = 1.0f / (float)N_SAMP;
    float cA = sx + half;          // col(u) = cA + u*dx
    float rA = half - sy;          // row(u) = rA - u*dy

    float dxs = dx * inv_s;
    float dys = -dy * inv_s;
    float cA0 = fmaf(0.5f, dxs, cA);   // col(i) = cA0 + i*dxs
    float rA0 = fmaf(0.5f, dys, rA);   // row(i) = rA0 + i*dys

    // orientation: fast axis = larger per-sample step (memory-contiguous quads)
    bool swp = fabsf(dys) > fabsf(dxs);
    const float4* __restrict__ base4 = swp ? g_quadT : g_quad;
    float fA0 = swp ? rA0 : cA0;
    float fds = swp ? dys : dxs;
    float gA0 = swp ? cA0 : rA0;
    float gds = swp ? dxs : dys;

    // outer clip: any sample that can contribute
    const float eps = 1e-3f;
    float u0 = 0.0f, u1 = 1.0f;
    clip_axis(cA,  dx, -1.0f - eps, (float)N_IMG + eps, u0, u1);
    clip_axis(rA, -dy, -1.0f - eps, (float)N_IMG + eps, u0, u1);

    // interior clip: all 4 texels guaranteed in-bounds
    float w0 = u0, w1 = u1;
    clip_axis(cA,  dx, 0.01f, 510.99f, w0, w1);
    clip_axis(rA, -dy, 0.01f, 510.99f, w0, w1);

    float acc = 0.0f;

    if (u0 <= u1) {
        int s0 = max(0, (int)floorf(u0 * (float)N_SAMP - 0.5f));
        int s1 = min(N_SAMP - 1, (int)ceilf(u1 * (float)N_SAMP - 0.5f));

        int iA, iB;
        if (w0 <= w1) {
            iA = max(s0, (int)ceilf (w0 * (float)N_SAMP - 0.5f));
            iB = min(s1, (int)floorf(w1 * (float)N_SAMP - 0.5f));
            if (iA > iB) { iA = s1 + 1; iB = s1; }
        } else {
            iA = s1 + 1;
            iB = s1;
        }

        // ---- masked prefix: [s0, iA)  (original img, row/col semantics) ----
        for (int i = s0 + lane; i < iA; i += 32) {
            float fi  = (float)i;
            float col = fmaf(fi, dxs, cA0);
            float row = fmaf(fi, dys, rA0);
            int r0 = __float2int_rd(row);
            int c0 = __float2int_rd(col);
            float fr = row - (float)r0;
            float fc = col - (float)c0;
            float v00 = fetch_masked(img, r0,     c0);
            float v01 = fetch_masked(img, r0,     c0 + 1);
            float v10 = fetch_masked(img, r0 + 1, c0);
            float v11 = fetch_masked(img, r0 + 1, c0 + 1);
            float top = fmaf(fc, v01 - v00, v00);
            float bot = fmaf(fc, v11 - v10, v10);
            acc      += fmaf(fr, bot - top, top);
        }

        // ---- fast interior: [iA, iB], ONE LDG.128 per sample ----
        #pragma unroll 4
        for (int i = iA + lane; i <= iB; i += 32) {
            float fi = (float)i;
            float fp = fmaf(fi, fds, fA0);
            float gp = fmaf(fi, gds, gA0);
            int f0 = __float2int_rd(fp);
            int g0 = __float2int_rd(gp);
            float wf = fp - (float)f0;
            float wg = gp - (float)g0;
            float4 q = __ldg(base4 + (g0 << 9) + f0);
            float top = fmaf(wf, q.y - q.x, q.x);
            float bot = fmaf(wf, q.w - q.z, q.z);
            acc      += fmaf(wg, bot - top, top);
        }

        // ---- masked suffix: (iB, s1] ----
        for (int i = iB + 1 + lane; i <= s1; i += 32) {
            float fi  = (float)i;
            float col = fmaf(fi, dxs, cA0);
            float row = fmaf(fi, dys, rA0);
            int r0 = __float2int_rd(row);
            int c0 = __float2int_rd(col);
            float fr = row - (float)r0;
            float fc = col - (float)c0;
            float v00 = fetch_masked(img, r0,     c0);
            float v01 = fetch_masked(img, r0,     c0 + 1);
            float v10 = fetch_masked(img, r0 + 1, c0);
            float v11 = fetch_masked(img, r0 + 1, c0 + 1);
            float top = fmaf(fc, v01 - v00, v00);
            float bot = fmaf(fc, v11 - v10, v10);
            acc      += fmaf(fr, bot - top, top);
        }
    }

    #pragma unroll
    for (int o = 16; o > 0; o >>= 1)
        acc += __shfl_down_sync(0xffffffffu, acc, o);

    if (lane == 0)
        out[gwarp] = acc * seg * inv_s;
}

extern "C" void kernel_launch(void* const* d_in, const int* in_sizes, int n_in,
                              void* d_out, int out_size) {
    (void)in_sizes; (void)n_in; (void)out_size;
    const float* img = (const float*)d_in[0];
    float* out = (float*)d_out;

    dim3 tb(32, 8);
    dim3 tg(N_IMG / 32, N_IMG / 32);
    prep_kernel<<<tg, tb>>>(img);

    fanbeam_kernel<<<N_RAYS / 8, 256>>>(img, out);
}

// round 6
// speedup vs baseline: 1.0860x; 1.0860x over previous
#include <cuda_runtime.h>
#include <math.h>

#define N_IMG   512
#define N_ANG   25
#define N_DET   512
#define N_SAMP  1024
#define N_RAYS  (N_ANG * N_DET)
#define TB      514              // bordered table dim: index = coord + 1, coord in [-1, 512]

#define SRC_DIST 512.0f
#define DET_DIST 512.0f
#define DET_SPACING 3.0f

// Bordered quad tables. Entry (gq,fq) holds the 4 bilinear texels for base
// coords g0=gq-1, f0=fq-1 with zero padding outside the image.
//  g_quadB : g = image row, f = image col  (.x=v(g,f) .y=v(g,f+1) .z=v(g+1,f) .w=v(g+1,f+1))
//  g_quadBT: g = image col, f = image row  (same contract in (g,f) space; v(g,f)=img[f][g])
__device__ float4 g_quadB [TB * TB];
__device__ float4 g_quadBT[TB * TB];

__global__ __launch_bounds__(256)
void prep_kernel(const float* __restrict__ img) {
    __shared__ float sm[33][33];    // stride 33 -> conflict-free for both access patterns
    int tx = threadIdx.x;           // 0..31
    int ty = threadIdx.y;           // 0..7
    int fbase = blockIdx.x * 32 - 1;   // f0 base for this tile
    int gbase = blockIdx.y * 32 - 1;   // g0 base
    int z = blockIdx.z;

    if (z == 0) {
        // sm[a][b] = img[gbase+a][fbase+b]  (rows coalesced over b)
        for (int a = ty; a < 33; a += 8) {
            int r = gbase + a;
            bool rok = (r >= 0) & (r < N_IMG);
            for (int b = tx; b < 33; b += 32) {
                int c = fbase + b;
                sm[a][b] = (rok && c >= 0 && c < N_IMG) ? img[r * N_IMG + c] : 0.0f;
            }
        }
    } else {
        // sm[a][b] = img[fbase+b][gbase+a]  (rows of img coalesced over a=tx)
        for (int b = ty; b < 33; b += 8) {
            int r = fbase + b;
            bool rok = (r >= 0) & (r < N_IMG);
            for (int a = tx; a < 33; a += 32) {
                int c = gbase + a;
                sm[a][b] = (rok && c >= 0 && c < N_IMG) ? img[r * N_IMG + c] : 0.0f;
            }
        }
    }
    __syncthreads();

    float4* __restrict__ dst = z ? g_quadBT : g_quadB;
    int fq = blockIdx.x * 32 + tx;
    if (fq < TB) {
        #pragma unroll
        for (int gg = ty; gg < 32; gg += 8) {
            int gq = blockIdx.y * 32 + gg;
            if (gq < TB)
                dst[gq * TB + fq] = make_float4(sm[gg][tx], sm[gg][tx + 1],
                                                sm[gg + 1][tx], sm[gg + 1][tx + 1]);
        }
    }
}

// shrink [u0,u1] so that p + u*v stays within [lo, hi] (fast divide; boundaries
// only gate samples whose bilinear weight vanishes, so approx divide is safe)
__device__ __forceinline__ void clip_axis(float p, float v, float lo, float hi,
                                          float& u0, float& u1) {
    if (fabsf(v) < 1e-12f) {
        if (p < lo || p > hi) { u0 = 1e30f; u1 = -1e30f; }
    } else {
        float inv = __fdividef(1.0f, v);
        float a = (lo - p) * inv;
        float b = (hi - p) * inv;
        float mn = fminf(a, b), mx = fmaxf(a, b);
        u0 = fmaxf(u0, mn);
        u1 = fminf(u1, mx);
    }
}

__global__ __launch_bounds__(256)
void fanbeam_kernel(float* __restrict__ out) {
    int gwarp = blockIdx.x * 8 + (threadIdx.x >> 5);
    int lane  = threadIdx.x & 31;

    int a = gwarp / N_DET;
    int d = gwarp - a * N_DET;

    float beta = (float)a * (2.0f * 3.14159265358979323846f / (float)N_ANG);
    float s, c;
    sincosf(beta, &s, &c);

    float t  = ((float)d - (float)(N_DET - 1) * 0.5f) * DET_SPACING;
    float sx = -SRC_DIST * s;
    float sy =  SRC_DIST * c;
    float dx = t * c + DET_DIST * s - sx;
    float dy = t * s - DET_DIST * c - sy;
    float seg = sqrtf(dx * dx + dy * dy);

    const float half  = (float)(N_IMG - 1) * 0.5f;   // 255.5
    const float inv_s = 1.0f / (float)N_SAMP;
    float cA = sx + half;          // col(u) = cA + u*dx
    float rA = half - sy;          // row(u) = rA - u*dy

    float dxs = dx * inv_s;
    float dys = -dy * inv_s;
    float cA0 = fmaf(0.5f, dxs, cA);   // col(i) = cA0 + i*dxs
    float rA0 = fmaf(0.5f, dys, rA);   // row(i) = rA0 + i*dys

    // orientation: fast axis = larger per-sample step
    bool swp = fabsf(dys) > fabsf(dxs);
    const float4* __restrict__ base4 = swp ? g_quadBT : g_quadB;
    float fA0 = swp ? rA0 : cA0;
    float fds = swp ? dys : dxs;
    float gA0 = swp ? cA0 : rA0;
    float gds = swp ? dxs : dys;

    // single clip: coords in [-0.998, 512] -> floor in [-1, 512], bordered
    // table covers it; contributions vanish continuously at both boundaries.
    float u0 = 0.0f, u1 = 1.0f;
    clip_axis(cA,  dx, -0.998f, 512.0f, u0, u1);
    clip_axis(rA, -dy, -0.998f, 512.0f, u0, u1);

    float acc = 0.0f;

    if (u0 <= u1) {
        int s0 = max(0,          (int)ceilf (u0 * (float)N_SAMP - 0.5f));
        int s1 = min(N_SAMP - 1, (int)floorf(u1 * (float)N_SAMP - 0.5f));

        #pragma unroll 4
        for (int i = s0 + lane; i <= s1; i += 32) {
            float fi = (float)i;
            float fp = fmaf(fi, fds, fA0);
            float gp = fmaf(fi, gds, gA0);
            int f0 = __float2int_rd(fp);
            int g0 = __float2int_rd(gp);
            float wf = fp - (float)f0;
            float wg = gp - (float)g0;
            float4 q = __ldg(base4 + (g0 * TB + f0 + (TB + 1)));
            float top = fmaf(wf, q.y - q.x, q.x);
            float bot = fmaf(wf, q.w - q.z, q.z);
            acc      += fmaf(wg, bot - top, top);
        }
    }

    #pragma unroll
    for (int o = 16; o > 0; o >>= 1)
        acc += __shfl_down_sync(0xffffffffu, acc, o);

    if (lane == 0)
        out[gwarp] = acc * seg * inv_s;
}

extern "C" void kernel_launch(void* const* d_in, const int* in_sizes, int n_in,
                              void* d_out, int out_size) {
    (void)in_sizes; (void)n_in; (void)out_size;
    const float* img = (const float*)d_in[0];
    float* out = (float*)d_out;

    dim3 tb(32, 8);
    dim3 tg(17, 17, 2);     // ceil(514/32) x ceil(514/32) x {quad, quadT}
    prep_kernel<<<tg, tb>>>(img);

    fanbeam_kernel<<<N_RAYS / 8, 256>>>(out);
}

// round 7
// speedup vs baseline: 1.1576x; 1.0659x over previous
#include <cuda_runtime.h>
#include <math.h>

#define N_IMG   512
#define N_ANG   25
#define N_DET   512
#define N_SAMP  1024
#define N_RAYS  (N_ANG * N_DET)
#define TB      514              // bordered table dim: index = coord + 1, coord in [-1, 512]

#define SRC_DIST 512.0f
#define DET_DIST 512.0f
#define DET_SPACING 3.0f

// Bordered quad tables. Entry (gq,fq) holds the 4 bilinear texels for base
// coords g0=gq-1, f0=fq-1 with zero padding outside the image.
//  g_quadB : g = image row, f = image col  (.x=v(g,f) .y=v(g,f+1) .z=v(g+1,f) .w=v(g+1,f+1))
//  g_quadBT: g = image col, f = image row  (v(g,f)=img[f][g])
__device__ float4 g_quadB [TB * TB];
__device__ float4 g_quadBT[TB * TB];

__global__ __launch_bounds__(256)
void prep_kernel(const float* __restrict__ img) {
    __shared__ float sm[33][33];
    int tx = threadIdx.x;              // 0..31
    int ty = threadIdx.y;              // 0..7
    int fbase = blockIdx.x * 32 - 1;   // f coord of sm[.][0]
    int gbase = blockIdx.y * 32 - 1;   // g coord of sm[0][.]
    int z = blockIdx.z;

    bool interior = (blockIdx.x > 0) & (blockIdx.y > 0) &
                    (fbase + 32 < N_IMG) & (gbase + 32 < N_IMG);

    if (interior) {
        if (z == 0) {
            #pragma unroll
            for (int a = ty; a < 33; a += 8) {
                const float* rp = img + (gbase + a) * N_IMG + fbase;
                sm[a][tx] = rp[tx];
                if (tx == 0) sm[a][32] = rp[32];
            }
        } else {
            #pragma unroll
            for (int b = ty; b < 33; b += 8) {
                const float* rp = img + (fbase + b) * N_IMG + gbase;
                sm[tx][b] = rp[tx];
                if (tx == 0) sm[32][b] = rp[32];
            }
        }
    } else {
        if (z == 0) {
            for (int a = ty; a < 33; a += 8) {
                int r = gbase + a;
                bool rok = (r >= 0) & (r < N_IMG);
                for (int b = tx; b < 33; b += 32) {
                    int c = fbase + b;
                    sm[a][b] = (rok && c >= 0 && c < N_IMG) ? img[r * N_IMG + c] : 0.0f;
                }
            }
        } else {
            for (int b = ty; b < 33; b += 8) {
                int r = fbase + b;
                bool rok = (r >= 0) & (r < N_IMG);
                for (int a = tx; a < 33; a += 32) {
                    int c = gbase + a;
                    sm[a][b] = (rok && c >= 0 && c < N_IMG) ? img[r * N_IMG + c] : 0.0f;
                }
            }
        }
    }
    __syncthreads();

    float4* __restrict__ dst = z ? g_quadBT : g_quadB;
    int fq = blockIdx.x * 32 + tx;
    if (fq < TB) {
        #pragma unroll
        for (int gg = ty; gg < 32; gg += 8) {
            int gq = blockIdx.y * 32 + gg;
            if (gq < TB)
                dst[gq * TB + fq] = make_float4(sm[gg][tx], sm[gg][tx + 1],
                                                sm[gg + 1][tx], sm[gg + 1][tx + 1]);
        }
    }
}

// shrink [u0,u1] so that p + u*v stays within [lo, hi]
__device__ __forceinline__ void clip_axis(float p, float v, float lo, float hi,
                                          float& u0, float& u1) {
    if (fabsf(v) < 1e-12f) {
        if (p < lo || p > hi) { u0 = 1e30f; u1 = -1e30f; }
    } else {
        float inv = __fdividef(1.0f, v);
        float a = (lo - p) * inv;
        float b = (hi - p) * inv;
        float mn = fminf(a, b), mx = fmaxf(a, b);
        u0 = fmaxf(u0, mn);
        u1 = fminf(u1, mx);
    }
}

__global__ __launch_bounds__(256)
void fanbeam_kernel(float* __restrict__ out) {
    int gwarp = blockIdx.x * 8 + (threadIdx.x >> 5);
    int lane  = threadIdx.x & 31;

    int a = gwarp >> 9;            // / N_DET (512)
    int d = gwarp & (N_DET - 1);

    float beta = (float)a * (2.0f * 3.14159265358979323846f / (float)N_ANG);
    float s, c;
    sincosf(beta, &s, &c);

    float t  = ((float)d - (float)(N_DET - 1) * 0.5f) * DET_SPACING;
    float sx = -SRC_DIST * s;
    float sy =  SRC_DIST * c;
    float dx = t * c + DET_DIST * s - sx;
    float dy = t * s - DET_DIST * c - sy;
    float seg = sqrtf(dx * dx + dy * dy);

    const float half  = (float)(N_IMG - 1) * 0.5f;   // 255.5
    const float inv_s = 1.0f / (float)N_SAMP;
    float cA = sx + half;          // col(u) = cA + u*dx
    float rA = half - sy;          // row(u) = rA - u*dy

    float dxs = dx * inv_s;
    float dys = -dy * inv_s;
    float cA0 = fmaf(0.5f, dxs, cA);
    float rA0 = fmaf(0.5f, dys, rA);

    // orientation: fast axis = larger per-sample step
    bool swp = fabsf(dys) > fabsf(dxs);
    float fA0 = swp ? rA0 : cA0;
    float fds = swp ? dys : dxs;
    float gA0 = swp ? cA0 : rA0;
    float gds = swp ? dxs : dys;

    // single clip: coords in [-0.998, 512] -> floor in [-1, 512]
    float u0 = 0.0f, u1 = 1.0f;
    clip_axis(cA,  dx, -0.998f, 512.0f, u0, u1);
    clip_axis(rA, -dy, -0.998f, 512.0f, u0, u1);

    int s0 = max(0,          (int)ceilf (u0 * (float)N_SAMP - 0.5f));
    int s1 = min(N_SAMP - 1, (int)floorf(u1 * (float)N_SAMP - 0.5f));
    bool live = (u0 <= u1);

    // ---- all setup done; wait for prep_kernel's tables (PDL) ----
#if __CUDA_ARCH__ >= 900
    cudaGridDependencySynchronize();
#endif

    const float4* __restrict__ tab =
        (swp ? g_quadBT : g_quadB) + (TB + 1);   // centered: index g0*TB + f0

    float acc = 0.0f;
    if (live) {
        #pragma unroll 4
        for (int i = s0 + lane; i <= s1; i += 32) {
            float fi = (float)i;
            float fp = fmaf(fi, fds, fA0);
            float gp = fmaf(fi, gds, gA0);
            int f0 = __float2int_rd(fp);
            int g0 = __float2int_rd(gp);
            float wf = fp - (float)f0;
            float wg = gp - (float)g0;
            float4 q = __ldg(tab + (g0 * TB + f0));
            float top = fmaf(wf, q.y - q.x, q.x);
            float bot = fmaf(wf, q.w - q.z, q.z);
            acc      += fmaf(wg, bot - top, top);
        }
    }

    #pragma unroll
    for (int o = 16; o > 0; o >>= 1)
        acc += __shfl_down_sync(0xffffffffu, acc, o);

    if (lane == 0)
        out[gwarp] = acc * seg * inv_s;
}

extern "C" void kernel_launch(void* const* d_in, const int* in_sizes, int n_in,
                              void* d_out, int out_size) {
    (void)in_sizes; (void)n_in; (void)out_size;
    const float* img = (const float*)d_in[0];
    float* out = (float*)d_out;

    dim3 tb(32, 8);
    dim3 tg(17, 17, 2);
    prep_kernel<<<tg, tb>>>(img);

    // secondary launch with programmatic stream serialization (PDL):
    // may start while prep is running; self-synchronizes via
    // cudaGridDependencySynchronize() after per-ray setup.
    cudaLaunchConfig_t cfg = {};
    cfg.gridDim  = dim3(N_RAYS / 8, 1, 1);
    cfg.blockDim = dim3(256, 1, 1);
    cfg.dynamicSmemBytes = 0;
    cudaLaunchAttribute attr[1];
    attr[0].id = cudaLaunchAttributeProgrammaticStreamSerialization;
    attr[0].val.programmaticStreamSerializationAllowed = 1;
    cfg.attrs = attr;
    cfg.numAttrs = 1;
    cudaLaunchKernelEx(&cfg, fanbeam_kernel, out);
}